// round 7
// baseline (speedup 1.0000x reference)
#include <cuda_runtime.h>
#include <cuda_bf16.h>
#include <cuda_fp16.h>
#include <stdint.h>

#define H 64

static const int MAXN = 100352;   // N = 100000 in dataset, padded
static const int MAXE = 1605632;  // E = 1600000 in dataset, padded
static const int SCAN_BLK = 1024;
static const int MAX_BLKS = (MAXN + SCAN_BLK - 1) / SCAN_BLK;  // 98 <= 128

// ---- device scratch (allocation-free contract: __device__ globals) ----
__device__ __align__(16) __half g_hh[(size_t)MAXN * H];  // h in fp16
__device__ float g_sdst[MAXN];                           // relu(agg) . w2
__device__ int g_cnt[MAXN];                              // per-row edge count
__device__ int g_part[MAXN];                             // scan partials
__device__ int g_bsum[MAX_BLKS + 32];                    // scan block sums
__device__ int g_start[MAXN + 1];                        // CSR row starts
__device__ int g_rank[MAXE];                             // within-row rank
__device__ __align__(16) int4 g_edge[MAXE];              // {col, v_bits, eid, 0}

__device__ __forceinline__ float neg_inf() {
    return __int_as_float(0xff800000);
}
__device__ __forceinline__ uint32_t f2tf32(float f) {
    uint32_t r;
    asm("cvt.rna.tf32.f32 %0, %1;" : "=r"(r) : "f"(f));
    return r;
}
__device__ __forceinline__ void mma_tf32(float c[4], uint32_t a0, uint32_t a1,
                                         uint32_t a2, uint32_t a3, uint32_t b0,
                                         uint32_t b1) {
    asm volatile(
        "mma.sync.aligned.m16n8k8.row.col.f32.tf32.tf32.f32 "
        "{%0,%1,%2,%3}, {%4,%5,%6,%7}, {%8,%9}, {%0,%1,%2,%3};"
        : "+f"(c[0]), "+f"(c[1]), "+f"(c[2]), "+f"(c[3])
        : "r"(a0), "r"(a1), "r"(a2), "r"(a3), "r"(b0), "r"(b1));
}

// ---------------------------------------------------------------- init
__global__ void init_kernel(int N) {
    int i = blockIdx.x * blockDim.x + threadIdx.x;
    int stride = gridDim.x * blockDim.x;
    for (int j = i; j < N; j += stride) g_cnt[j] = 0;
}

// ------------------------------------------------------------ tf32 GEMM
// h[N,64] = feat[N,F] @ W[F,64] + b, stored fp16. Block tile 128x64,
// 8 warps (4Mx2N), warp tile 32x32 = 2x4 m16n8k8 mma.
__global__ void gemm_tf32_kernel(const float* __restrict__ feat,
                                 const float* __restrict__ W,
                                 const float* __restrict__ bias,
                                 int N, int F) {
    extern __shared__ uint32_t smem[];
    uint32_t* sW = smem;          // F*64 entries
    uint32_t* sA = smem + F * H;  // 8 chunks * 516

    int tid = threadIdx.x;
    int lane = tid & 31, wid = tid >> 5;
    int gid = lane >> 2, tig = lane & 3;
    int mbase = (wid >> 1) * 32;
    int nbase = (wid & 1) * 32;
    int rowBase = blockIdx.x * 128;

    int nIterW = (F * H / 4) / 256;  // F/16
    for (int it = 0; it < nIterW; it++) {
        int idx4 = it * 256 + tid;
        int k = idx4 >> 4;
        int n4 = (idx4 & 15) * 4;
        float4 w4 = ((const float4*)W)[idx4];
        uint32_t base = (k >> 2) * 256 + (k & 3);
        sW[base + (n4 + 0) * 4] = f2tf32(w4.x);
        sW[base + (n4 + 1) * 4] = f2tf32(w4.y);
        sW[base + (n4 + 2) * 4] = f2tf32(w4.z);
        sW[base + (n4 + 3) * 4] = f2tf32(w4.w);
    }

    float acc[2][4][4];
#pragma unroll
    for (int mt = 0; mt < 2; mt++)
#pragma unroll
        for (int nt = 0; nt < 4; nt++)
#pragma unroll
            for (int j = 0; j < 4; j++) acc[mt][nt][j] = 0.0f;

    int nkb = F / 32;
    for (int kb = 0; kb < nkb; kb++) {
        __syncthreads();
#pragma unroll
        for (int i = 0; i < 4; i++) {
            int fid = i * 256 + tid;
            int row = fid >> 3;
            int q = fid & 7;
            int grow = rowBase + row;
            float4 a = make_float4(0.f, 0.f, 0.f, 0.f);
            if (grow < N)
                a = ((const float4*)(feat + (size_t)grow * F + kb * 32))[q];
            uint32_t* dst = sA + q * 516 + row * 4;
            dst[0] = f2tf32(a.x);
            dst[1] = f2tf32(a.y);
            dst[2] = f2tf32(a.z);
            dst[3] = f2tf32(a.w);
        }
        __syncthreads();

#pragma unroll
        for (int ks = 0; ks < 4; ks++) {
            int kc0 = ks * 2, kc1 = kc0 + 1;
            int kg0 = kb * 8 + kc0, kg1 = kg0 + 1;
            uint32_t b0[4], b1[4];
#pragma unroll
            for (int nt = 0; nt < 4; nt++) {
                int c = nbase + nt * 8 + gid;
                b0[nt] = sW[kg0 * 256 + c * 4 + tig];
                b1[nt] = sW[kg1 * 256 + c * 4 + tig];
            }
#pragma unroll
            for (int mt = 0; mt < 2; mt++) {
                int r = mbase + mt * 16 + gid;
                uint32_t a0 = sA[kc0 * 516 + r * 4 + tig];
                uint32_t a1 = sA[kc0 * 516 + (r + 8) * 4 + tig];
                uint32_t a2 = sA[kc1 * 516 + r * 4 + tig];
                uint32_t a3 = sA[kc1 * 516 + (r + 8) * 4 + tig];
#pragma unroll
                for (int nt = 0; nt < 4; nt++)
                    mma_tf32(acc[mt][nt], a0, a1, a2, a3, b0[nt], b1[nt]);
            }
        }
    }

#pragma unroll
    for (int mt = 0; mt < 2; mt++) {
        int r0 = rowBase + mbase + mt * 16 + gid;
        int r1 = r0 + 8;
#pragma unroll
        for (int nt = 0; nt < 4; nt++) {
            int c = nbase + nt * 8 + 2 * tig;
            float bx = __ldg(bias + c), by = __ldg(bias + c + 1);
            if (r0 < N)
                *(__half2*)&g_hh[(size_t)r0 * H + c] =
                    __floats2half2_rn(acc[mt][nt][0] + bx,
                                      acc[mt][nt][1] + by);
            if (r1 < N)
                *(__half2*)&g_hh[(size_t)r1 * H + c] =
                    __floats2half2_rn(acc[mt][nt][2] + bx,
                                      acc[mt][nt][3] + by);
        }
    }
}

// ------------------------------------------------------------- CSR build
// hist also records each edge's within-row rank -> scatter needs no atomic.
__global__ void hist_kernel(const int* __restrict__ row_idx, int E) {
    int i = blockIdx.x * blockDim.x + threadIdx.x;
    int stride = gridDim.x * blockDim.x;
    int E4 = E >> 2;
    const int4* r4 = (const int4*)row_idx;
    for (int e = i; e < E4; e += stride) {
        int4 r = r4[e];
        int base = e * 4;
        g_rank[base + 0] = atomicAdd(&g_cnt[r.x], 1);
        g_rank[base + 1] = atomicAdd(&g_cnt[r.y], 1);
        g_rank[base + 2] = atomicAdd(&g_cnt[r.z], 1);
        g_rank[base + 3] = atomicAdd(&g_cnt[r.w], 1);
    }
    for (int e = E4 * 4 + i; e < E; e += stride)
        g_rank[e] = atomicAdd(&g_cnt[row_idx[e]], 1);
}

// shuffle-based inclusive scan within 1024-element blocks
__global__ void scan1_kernel(int N) {
    __shared__ int wsum[32];
    int tid = threadIdx.x;
    int lane = tid & 31, wid = tid >> 5;
    int i = blockIdx.x * SCAN_BLK + tid;
    int x = (i < N) ? g_cnt[i] : 0;
#pragma unroll
    for (int off = 1; off < 32; off <<= 1) {
        int t = __shfl_up_sync(0xFFFFFFFFu, x, off);
        if (lane >= off) x += t;
    }
    if (lane == 31) wsum[wid] = x;
    __syncthreads();
    if (wid == 0) {
        int s = wsum[lane];
#pragma unroll
        for (int off = 1; off < 32; off <<= 1) {
            int t = __shfl_up_sync(0xFFFFFFFFu, s, off);
            if (lane >= off) s += t;
        }
        wsum[lane] = s;
    }
    __syncthreads();
    if (wid > 0) x += wsum[wid - 1];
    if (i < N) g_part[i] = x;
    if (tid == SCAN_BLK - 1) g_bsum[blockIdx.x] = x;
}

// parallel exclusive scan of block sums (nb <= 128)
__global__ void scan2_kernel(int nb) {
    __shared__ int sh[128];
    int t = threadIdx.x;
    int v = (t < nb) ? g_bsum[t] : 0;
    sh[t] = v;
    __syncthreads();
#pragma unroll
    for (int off = 1; off < 128; off <<= 1) {
        int u = (t >= off) ? sh[t - off] : 0;
        __syncthreads();
        sh[t] += u;
        __syncthreads();
    }
    if (t < nb) g_bsum[t] = sh[t] - v;  // exclusive
}

__global__ void scan3_kernel(int N, int E) {
    int i = blockIdx.x * blockDim.x + threadIdx.x;
    if (i >= N) return;
    g_start[i] = g_bsum[i >> 10] + g_part[i] - g_cnt[i];
    if (i == N - 1) g_start[N] = E;
}

// atomic-free scatter: position = start[row] + rank[e]
__global__ void scatter_kernel(const int* __restrict__ row_idx,
                               const int* __restrict__ col_idx,
                               const float* __restrict__ vv, int E) {
    int i = blockIdx.x * blockDim.x + threadIdx.x;
    int stride = gridDim.x * blockDim.x;
    int E4 = E >> 2;
    const int4* r4 = (const int4*)row_idx;
    const int4* c4 = (const int4*)col_idx;
    const float4* v4 = (const float4*)vv;
    const int4* k4 = (const int4*)g_rank;
    for (int e = i; e < E4; e += stride) {
        int4 r = r4[e];
        int4 c = c4[e];
        float4 v = v4[e];
        int4 k = k4[e];
        int base = e * 4;
        g_edge[g_start[r.x] + k.x] =
            make_int4(c.x, __float_as_int(v.x), base + 0, 0);
        g_edge[g_start[r.y] + k.y] =
            make_int4(c.y, __float_as_int(v.y), base + 1, 0);
        g_edge[g_start[r.z] + k.z] =
            make_int4(c.z, __float_as_int(v.z), base + 2, 0);
        g_edge[g_start[r.w] + k.w] =
            make_int4(c.w, __float_as_int(v.w), base + 3, 0);
    }
    for (int e = E4 * 4 + i; e < E; e += stride)
        g_edge[g_start[row_idx[e]] + g_rank[e]] =
            make_int4(col_idx[e], __float_as_int(vv[e]), e, 0);
}

// -------------------------------------------------- fused agg + sdst
// One warp per row; FOUR quarter-warps (8 lanes) each handle one edge,
// lane loads uint4 = 8 fp16 features. 4 edges in flight per warp (MLP=4).
__global__ void agg_sdst_kernel(const float* __restrict__ wmlp, int N) {
    int w = (blockIdx.x * blockDim.x + threadIdx.x) >> 5;
    if (w >= N) return;
    int lane = threadIdx.x & 31;
    int grp = lane >> 3;  // 0..3 quarter-warp
    int sub = lane & 7;   // 0..7 feature slice

    int s = g_start[w];
    int eend = g_start[w + 1];

    float acc[8];
#pragma unroll
    for (int j = 0; j < 8; j++) acc[j] = 0.0f;

    for (int p = s + grp; p < eend; p += 4) {
        int4 ed = g_edge[p];  // broadcast within quarter-warp
        float v = __int_as_float(ed.y);
        uint4 u = *(const uint4*)(g_hh + (size_t)ed.x * H + sub * 8);
        float2 f0 = __half22float2(*(const __half2*)&u.x);
        float2 f1 = __half22float2(*(const __half2*)&u.y);
        float2 f2 = __half22float2(*(const __half2*)&u.z);
        float2 f3 = __half22float2(*(const __half2*)&u.w);
        acc[0] = fmaf(v, f0.x, acc[0]);
        acc[1] = fmaf(v, f0.y, acc[1]);
        acc[2] = fmaf(v, f1.x, acc[2]);
        acc[3] = fmaf(v, f1.y, acc[3]);
        acc[4] = fmaf(v, f2.x, acc[4]);
        acc[5] = fmaf(v, f2.y, acc[5]);
        acc[6] = fmaf(v, f3.x, acc[6]);
        acc[7] = fmaf(v, f3.y, acc[7]);
    }
    // combine the four quarter-warps: lanes 0..7 end with full sums
#pragma unroll
    for (int j = 0; j < 8; j++) {
        acc[j] += __shfl_down_sync(0xFFFFFFFFu, acc[j], 16);
        acc[j] += __shfl_down_sync(0xFFFFFFFFu, acc[j], 8);
    }

    float pd = 0.0f;
    if (lane < 8) {
        float4 wa = *(const float4*)(wmlp + H + lane * 8);
        float4 wb = *(const float4*)(wmlp + H + lane * 8 + 4);
        pd = fmaxf(acc[0], 0.f) * wa.x + fmaxf(acc[1], 0.f) * wa.y +
             fmaxf(acc[2], 0.f) * wa.z + fmaxf(acc[3], 0.f) * wa.w +
             fmaxf(acc[4], 0.f) * wb.x + fmaxf(acc[5], 0.f) * wb.y +
             fmaxf(acc[6], 0.f) * wb.z + fmaxf(acc[7], 0.f) * wb.w;
    }
#pragma unroll
    for (int o = 4; o; o >>= 1) pd += __shfl_down_sync(0xFFFFFFFFu, pd, o);
    if (lane == 0) g_sdst[w] = pd;
}

// -------------------------------------------- fused softmax + output
// s_src[row] cancels in the row-segment softmax -> scores = sdst[col].
__global__ void softmax_out_kernel(float* __restrict__ out, int N) {
    int w = (blockIdx.x * blockDim.x + threadIdx.x) >> 5;
    if (w >= N) return;
    int lane = threadIdx.x & 31;
    int s = g_start[w];
    int eend = g_start[w + 1];
    int n = eend - s;
    if (n == 0) return;

    if (n <= 32) {
        int p = s + lane;
        bool act = p < eend;
        int4 ed = act ? g_edge[p] : make_int4(0, 0, 0, 0);
        float sc = act ? g_sdst[ed.x] : neg_inf();
        float m = sc;
#pragma unroll
        for (int o = 16; o; o >>= 1)
            m = fmaxf(m, __shfl_xor_sync(0xFFFFFFFFu, m, o));
        float ex = act ? __expf(sc - m) : 0.0f;
        float z = ex;
#pragma unroll
        for (int o = 16; o; o >>= 1) z += __shfl_xor_sync(0xFFFFFFFFu, z, o);
        if (act) out[ed.z] = __int_as_float(ed.y) + ex / z;
    } else {
        float m = neg_inf();
        for (int p = s + lane; p < eend; p += 32)
            m = fmaxf(m, g_sdst[g_edge[p].x]);
#pragma unroll
        for (int o = 16; o; o >>= 1)
            m = fmaxf(m, __shfl_xor_sync(0xFFFFFFFFu, m, o));
        float z = 0.0f;
        for (int p = s + lane; p < eend; p += 32)
            z += __expf(g_sdst[g_edge[p].x] - m);
#pragma unroll
        for (int o = 16; o; o >>= 1) z += __shfl_xor_sync(0xFFFFFFFFu, z, o);
        float inv_z = 1.0f / z;
        for (int p = s + lane; p < eend; p += 32) {
            int4 ed = g_edge[p];
            out[ed.z] =
                __int_as_float(ed.y) + __expf(g_sdst[ed.x] - m) * inv_z;
        }
    }
}

// ---------------------------------------------------------------- launch
extern "C" void kernel_launch(void* const* d_in, const int* in_sizes, int n_in,
                              void* d_out, int out_size) {
    const float* feat = (const float*)d_in[0];
    const float* vv = (const float*)d_in[1];
    const float* W = (const float*)d_in[2];
    const float* bg = (const float*)d_in[3];
    const float* wm = (const float*)d_in[4];
    // d_in[5] = b_mlp: cancels in softmax; unused.
    const int* vidx = (const int*)d_in[6];  // int32 (JAX x64 disabled)

    int F = in_sizes[2] / H;  // 256
    int N = in_sizes[0] / F;  // 100000
    int E = in_sizes[1];      // 1600000
    const int* row_idx = vidx;
    const int* col_idx = vidx + E;
    float* out = (float*)d_out;

    int eb4 = (E / 4 + 255) / 256;
    int nb = (N + 255) / 256;
    int nscan = (N + SCAN_BLK - 1) / SCAN_BLK;
    int wb = (N * 32 + 255) / 256;  // warp-per-row grids

    size_t gemm_smem = (size_t)(F * H + 8 * 516) * 4;  // tf32 W + A chunk
    cudaFuncSetAttribute(gemm_tf32_kernel,
                         cudaFuncAttributeMaxDynamicSharedMemorySize,
                         (int)gemm_smem);

    init_kernel<<<512, 256>>>(N);
    gemm_tf32_kernel<<<(N + 127) / 128, 256, gemm_smem>>>(feat, W, bg, N, F);
    hist_kernel<<<eb4, 256>>>(row_idx, E);
    scan1_kernel<<<nscan, SCAN_BLK>>>(N);
    scan2_kernel<<<1, 128>>>(nscan);
    scan3_kernel<<<nb, 256>>>(N, E);
    scatter_kernel<<<eb4, 256>>>(row_idx, col_idx, vv, E);
    agg_sdst_kernel<<<wb, 256>>>(wm, N);
    softmax_out_kernel<<<wb, 256>>>(out, N);
}

// round 8
// speedup vs baseline: 1.0841x; 1.0841x over previous
#include <cuda_runtime.h>
#include <cuda_bf16.h>
#include <cuda_fp16.h>
#include <stdint.h>

#define H 64

static const int MAXN = 100352;   // N = 100000 in dataset, padded
static const int MAXE = 1605632;  // E = 1600000 in dataset, padded
static const int SCAN_BLK = 1024;
static const int MAX_BLKS = (MAXN + SCAN_BLK - 1) / SCAN_BLK;  // 98 <= 128
static const int SCAN_FLAG = 1 << 30;

// ---- device scratch (allocation-free contract: __device__ globals) ----
__device__ __align__(16) __half g_hh[(size_t)MAXN * H];  // h in fp16
__device__ float g_sdst[MAXN];                           // relu(agg) . w2
__device__ __align__(8) float2 g_mz[MAXN];               // per-row {max, Z}
__device__ int g_cnt[MAXN];                              // per-row edge count
__device__ int g_bagg[MAX_BLKS + 32];                    // scan aggregates+flag
__device__ int g_start[MAXN + 1];                        // CSR row starts
__device__ int g_rank[MAXE];                             // within-row rank
__device__ __align__(8) int2 g_ecsr[MAXE];               // CSR {col, v_bits}

__device__ __forceinline__ float neg_inf() {
    return __int_as_float(0xff800000);
}
__device__ __forceinline__ uint32_t f2tf32(float f) {
    uint32_t r;
    asm("cvt.rna.tf32.f32 %0, %1;" : "=r"(r) : "f"(f));
    return r;
}
__device__ __forceinline__ void mma_tf32(float c[4], uint32_t a0, uint32_t a1,
                                         uint32_t a2, uint32_t a3, uint32_t b0,
                                         uint32_t b1) {
    asm volatile(
        "mma.sync.aligned.m16n8k8.row.col.f32.tf32.tf32.f32 "
        "{%0,%1,%2,%3}, {%4,%5,%6,%7}, {%8,%9}, {%0,%1,%2,%3};"
        : "+f"(c[0]), "+f"(c[1]), "+f"(c[2]), "+f"(c[3])
        : "r"(a0), "r"(a1), "r"(a2), "r"(a3), "r"(b0), "r"(b1));
}

// ---------------------------------------------------------------- init
__global__ void init_kernel(int N) {
    int i = blockIdx.x * blockDim.x + threadIdx.x;
    int stride = gridDim.x * blockDim.x;
    for (int j = i; j < N; j += stride) g_cnt[j] = 0;
    for (int j = i; j < MAX_BLKS + 32; j += stride) g_bagg[j] = 0;
}

// -------------------------------------- fused tf32 GEMM | hist (block spec)
// Blocks [0, G): GEMM h = feat@W + b, fp16 out. Block tile 128x64, 8 warps
// (4Mx2N), warp tile 32x32 = 2x4 m16n8k8. A staged in smem (16.5KB); W (64KB,
// L1/L2-resident) read directly from global as tf32 b-fragments.
// Blocks [G, ...): hist — per-row edge counts + per-edge within-row rank.
// The two groups touch disjoint resources (DRAM stream vs L2 atomics) and
// overlap inside one launch without streams.
__global__ void __launch_bounds__(256) gemm_hist_kernel(
    const float* __restrict__ feat, const float* __restrict__ W,
    const float* __restrict__ bias, const int* __restrict__ row_idx, int N,
    int F, int E, int G) {
    extern __shared__ uint32_t sA[];  // 8 chunks * 516

    if (blockIdx.x >= G) {
        // ---------------- hist part ----------------
        int hb = blockIdx.x - G;
        int nhb = gridDim.x - G;
        int i = hb * blockDim.x + threadIdx.x;
        int stride = nhb * blockDim.x;
        int E4 = E >> 2;
        const int4* r4 = (const int4*)row_idx;
        for (int e = i; e < E4; e += stride) {
            int4 r = r4[e];
            int base = e * 4;
            g_rank[base + 0] = atomicAdd(&g_cnt[r.x], 1);
            g_rank[base + 1] = atomicAdd(&g_cnt[r.y], 1);
            g_rank[base + 2] = atomicAdd(&g_cnt[r.z], 1);
            g_rank[base + 3] = atomicAdd(&g_cnt[r.w], 1);
        }
        for (int e = E4 * 4 + i; e < E; e += stride)
            g_rank[e] = atomicAdd(&g_cnt[row_idx[e]], 1);
        return;
    }

    // ---------------- GEMM part ----------------
    int tid = threadIdx.x;
    int lane = tid & 31, wid = tid >> 5;
    int gid = lane >> 2, tig = lane & 3;
    int mbase = (wid >> 1) * 32;
    int nbase = (wid & 1) * 32;
    int rowBase = blockIdx.x * 128;

    float acc[2][4][4];
#pragma unroll
    for (int mt = 0; mt < 2; mt++)
#pragma unroll
        for (int nt = 0; nt < 4; nt++)
#pragma unroll
            for (int j = 0; j < 4; j++) acc[mt][nt][j] = 0.0f;

    int nkb = F / 32;
    for (int kb = 0; kb < nkb; kb++) {
        __syncthreads();
#pragma unroll
        for (int i = 0; i < 4; i++) {
            int fid = i * 256 + tid;
            int row = fid >> 3;
            int q = fid & 7;
            int grow = rowBase + row;
            float4 a = make_float4(0.f, 0.f, 0.f, 0.f);
            if (grow < N)
                a = ((const float4*)(feat + (size_t)grow * F + kb * 32))[q];
            uint32_t* dst = sA + q * 516 + row * 4;
            dst[0] = f2tf32(a.x);
            dst[1] = f2tf32(a.y);
            dst[2] = f2tf32(a.z);
            dst[3] = f2tf32(a.w);
        }
        __syncthreads();

#pragma unroll
        for (int ks = 0; ks < 4; ks++) {
            int kc0 = ks * 2, kc1 = kc0 + 1;
            int kg0 = kb * 8 + kc0, kg1 = kg0 + 1;
            uint32_t b0[4], b1[4];
#pragma unroll
            for (int nt = 0; nt < 4; nt++) {
                int c = nbase + nt * 8 + gid;
                b0[nt] = f2tf32(__ldg(W + (size_t)(kg0 * 4 + tig) * H + c));
                b1[nt] = f2tf32(__ldg(W + (size_t)(kg1 * 4 + tig) * H + c));
            }
#pragma unroll
            for (int mt = 0; mt < 2; mt++) {
                int r = mbase + mt * 16 + gid;
                uint32_t a0 = sA[kc0 * 516 + r * 4 + tig];
                uint32_t a1 = sA[kc0 * 516 + (r + 8) * 4 + tig];
                uint32_t a2 = sA[kc1 * 516 + r * 4 + tig];
                uint32_t a3 = sA[kc1 * 516 + (r + 8) * 4 + tig];
#pragma unroll
                for (int nt = 0; nt < 4; nt++)
                    mma_tf32(acc[mt][nt], a0, a1, a2, a3, b0[nt], b1[nt]);
            }
        }
    }

#pragma unroll
    for (int mt = 0; mt < 2; mt++) {
        int r0 = rowBase + mbase + mt * 16 + gid;
        int r1 = r0 + 8;
#pragma unroll
        for (int nt = 0; nt < 4; nt++) {
            int c = nbase + nt * 8 + 2 * tig;
            float bx = __ldg(bias + c), by = __ldg(bias + c + 1);
            if (r0 < N)
                *(__half2*)&g_hh[(size_t)r0 * H + c] =
                    __floats2half2_rn(acc[mt][nt][0] + bx,
                                      acc[mt][nt][1] + by);
            if (r1 < N)
                *(__half2*)&g_hh[(size_t)r1 * H + c] =
                    __floats2half2_rn(acc[mt][nt][2] + bx,
                                      acc[mt][nt][3] + by);
        }
    }
}

// ------------------------------- single-kernel scan (decoupled lookback)
// 98 blocks, all co-resident on 148 SMs. Each block: shuffle scan of its
// 1024 counts, publish aggregate with flag bit, warp 0 sums all
// predecessor aggregates (spin until published), write g_start directly.
__global__ void scan_kernel(int N, int E) {
    __shared__ int wsum[32];
    __shared__ int s_off;
    int tid = threadIdx.x;
    int lane = tid & 31, wid = tid >> 5;
    int bid = blockIdx.x;
    int i = bid * SCAN_BLK + tid;
    int c = (i < N) ? g_cnt[i] : 0;
    int x = c;
#pragma unroll
    for (int off = 1; off < 32; off <<= 1) {
        int t = __shfl_up_sync(0xFFFFFFFFu, x, off);
        if (lane >= off) x += t;
    }
    if (lane == 31) wsum[wid] = x;
    __syncthreads();
    if (wid == 0) {
        int s = wsum[lane];
#pragma unroll
        for (int off = 1; off < 32; off <<= 1) {
            int t = __shfl_up_sync(0xFFFFFFFFu, s, off);
            if (lane >= off) s += t;
        }
        wsum[lane] = s;
    }
    __syncthreads();
    if (wid > 0) x += wsum[wid - 1];

    // publish this block's aggregate (single word carries value + flag)
    if (tid == SCAN_BLK - 1) atomicExch(&g_bagg[bid], x | SCAN_FLAG);

    // lookback: warp 0 sums predecessors
    if (wid == 0) {
        int sum = 0;
        for (int t = lane; t < bid; t += 32) {
            int v;
            do {
                v = ((volatile int*)g_bagg)[t];
            } while (!(v & SCAN_FLAG));
            sum += v & ~SCAN_FLAG;
        }
#pragma unroll
        for (int o = 16; o; o >>= 1)
            sum += __shfl_xor_sync(0xFFFFFFFFu, sum, o);
        if (lane == 0) s_off = sum;
    }
    __syncthreads();
    int off = s_off;
    if (i < N) g_start[i] = off + x - c;  // exclusive prefix
    if (i == N - 1) g_start[N] = E;
}

// atomic-free scatter: position = start[row] + rank[e]; 8B records {col,v}
__global__ void scatter_kernel(const int* __restrict__ row_idx,
                               const int* __restrict__ col_idx,
                               const float* __restrict__ vv, int E) {
    int i = blockIdx.x * blockDim.x + threadIdx.x;
    int stride = gridDim.x * blockDim.x;
    int E4 = E >> 2;
    const int4* r4 = (const int4*)row_idx;
    const int4* c4 = (const int4*)col_idx;
    const float4* v4 = (const float4*)vv;
    const int4* k4 = (const int4*)g_rank;
    for (int e = i; e < E4; e += stride) {
        int4 r = r4[e];
        int4 c = c4[e];
        float4 v = v4[e];
        int4 k = k4[e];
        g_ecsr[g_start[r.x] + k.x] = make_int2(c.x, __float_as_int(v.x));
        g_ecsr[g_start[r.y] + k.y] = make_int2(c.y, __float_as_int(v.y));
        g_ecsr[g_start[r.z] + k.z] = make_int2(c.z, __float_as_int(v.z));
        g_ecsr[g_start[r.w] + k.w] = make_int2(c.w, __float_as_int(v.w));
    }
    for (int e = E4 * 4 + i; e < E; e += stride)
        g_ecsr[g_start[row_idx[e]] + g_rank[e]] =
            make_int2(col_idx[e], __float_as_int(vv[e]));
}

// -------------------------------------------------- fused agg + sdst
// One warp per row; two half-warps each handle one edge at a time,
// 16 lanes x 4 fp16 features (8B load) = 64. fp32 accumulate, relu, dot w2.
__global__ void agg_sdst_kernel(const float* __restrict__ wmlp, int N) {
    int w = (blockIdx.x * blockDim.x + threadIdx.x) >> 5;
    if (w >= N) return;
    int lane = threadIdx.x & 31;
    int half = lane >> 4;
    int seg = lane & 15;

    int s = g_start[w];
    int eend = g_start[w + 1];

    float4 acc = make_float4(0.f, 0.f, 0.f, 0.f);
    for (int p = s + half; p < eend; p += 2) {
        int2 ed = g_ecsr[p];  // broadcast within half-warp
        float v = __int_as_float(ed.y);
        uint2 u = *(const uint2*)(g_hh + (size_t)ed.x * H + seg * 4);
        float2 f01 = __half22float2(*(const __half2*)&u.x);
        float2 f23 = __half22float2(*(const __half2*)&u.y);
        acc.x = fmaf(v, f01.x, acc.x);
        acc.y = fmaf(v, f01.y, acc.y);
        acc.z = fmaf(v, f23.x, acc.z);
        acc.w = fmaf(v, f23.y, acc.w);
    }
    acc.x += __shfl_down_sync(0xFFFFFFFFu, acc.x, 16);
    acc.y += __shfl_down_sync(0xFFFFFFFFu, acc.y, 16);
    acc.z += __shfl_down_sync(0xFFFFFFFFu, acc.z, 16);
    acc.w += __shfl_down_sync(0xFFFFFFFFu, acc.w, 16);

    float pd = 0.0f;
    if (half == 0) {
        float4 w2 = *(const float4*)(wmlp + H + seg * 4);
        pd = fmaxf(acc.x, 0.f) * w2.x + fmaxf(acc.y, 0.f) * w2.y +
             fmaxf(acc.z, 0.f) * w2.z + fmaxf(acc.w, 0.f) * w2.w;
    }
#pragma unroll
    for (int o = 8; o; o >>= 1) pd += __shfl_down_sync(0xFFFFFFFFu, pd, o);
    if (lane == 0) g_sdst[w] = pd;
}

// ---------------------------------------- per-row softmax stats (m, Z)
// s_src[row] cancels in the row-segment softmax -> scores = sdst[col].
__global__ void mz_kernel(int N) {
    int w = (blockIdx.x * blockDim.x + threadIdx.x) >> 5;
    if (w >= N) return;
    int lane = threadIdx.x & 31;
    int s = g_start[w];
    int eend = g_start[w + 1];
    int n = eend - s;
    if (n == 0) return;

    float m, z;
    if (n <= 32) {
        int p = s + lane;
        bool act = p < eend;
        float sc = act ? g_sdst[g_ecsr[p].x] : neg_inf();
        m = sc;
#pragma unroll
        for (int o = 16; o; o >>= 1)
            m = fmaxf(m, __shfl_xor_sync(0xFFFFFFFFu, m, o));
        float ex = act ? __expf(sc - m) : 0.0f;
        z = ex;
#pragma unroll
        for (int o = 16; o; o >>= 1) z += __shfl_xor_sync(0xFFFFFFFFu, z, o);
    } else {
        m = neg_inf();
        for (int p = s + lane; p < eend; p += 32)
            m = fmaxf(m, g_sdst[g_ecsr[p].x]);
#pragma unroll
        for (int o = 16; o; o >>= 1)
            m = fmaxf(m, __shfl_xor_sync(0xFFFFFFFFu, m, o));
        z = 0.0f;
        for (int p = s + lane; p < eend; p += 32)
            z += __expf(g_sdst[g_ecsr[p].x] - m);
#pragma unroll
        for (int o = 16; o; o >>= 1) z += __shfl_xor_sync(0xFFFFFFFFu, z, o);
    }
    if (lane == 0) g_mz[w] = make_float2(m, z);
}

// -------------------------- final pass in ORIGINAL edge order (coalesced)
// out[e] = v[e] + exp(sdst[col] - m[row]) / z[row]
__global__ void final_kernel(const int* __restrict__ row_idx,
                             const int* __restrict__ col_idx,
                             const float* __restrict__ vv,
                             float* __restrict__ out, int E) {
    int i = blockIdx.x * blockDim.x + threadIdx.x;
    int stride = gridDim.x * blockDim.x;
    int E4 = E >> 2;
    const int4* r4 = (const int4*)row_idx;
    const int4* c4 = (const int4*)col_idx;
    const float4* v4 = (const float4*)vv;
    float4* o4 = (float4*)out;
    for (int e = i; e < E4; e += stride) {
        int4 r = r4[e];
        int4 c = c4[e];
        float4 v = v4[e];
        float2 mz0 = g_mz[r.x], mz1 = g_mz[r.y];
        float2 mz2 = g_mz[r.z], mz3 = g_mz[r.w];
        float s0 = g_sdst[c.x], s1 = g_sdst[c.y];
        float s2 = g_sdst[c.z], s3 = g_sdst[c.w];
        float4 o;
        o.x = v.x + __expf(s0 - mz0.x) / mz0.y;
        o.y = v.y + __expf(s1 - mz1.x) / mz1.y;
        o.z = v.z + __expf(s2 - mz2.x) / mz2.y;
        o.w = v.w + __expf(s3 - mz3.x) / mz3.y;
        o4[e] = o;
    }
    for (int e = E4 * 4 + i; e < E; e += stride) {
        float2 mz = g_mz[row_idx[e]];
        out[e] = vv[e] + __expf(g_sdst[col_idx[e]] - mz.x) / mz.y;
    }
}

// ---------------------------------------------------------------- launch
extern "C" void kernel_launch(void* const* d_in, const int* in_sizes, int n_in,
                              void* d_out, int out_size) {
    const float* feat = (const float*)d_in[0];
    const float* vv = (const float*)d_in[1];
    const float* W = (const float*)d_in[2];
    const float* bg = (const float*)d_in[3];
    const float* wm = (const float*)d_in[4];
    // d_in[5] = b_mlp: cancels in softmax; unused.
    const int* vidx = (const int*)d_in[6];  // int32 (JAX x64 disabled)

    int F = in_sizes[2] / H;  // 256
    int N = in_sizes[0] / F;  // 100000
    int E = in_sizes[1];      // 1600000
    const int* row_idx = vidx;
    const int* col_idx = vidx + E;
    float* out = (float*)d_out;

    int G = (N + 127) / 128;          // gemm blocks
    int HB = 1024;                    // hist blocks
    int eb4 = (E / 4 + 255) / 256;
    int nscan = (N + SCAN_BLK - 1) / SCAN_BLK;
    int wb = (N * 32 + 255) / 256;    // warp-per-row grids

    size_t smem = (size_t)(8 * 516) * 4;  // A staging only (16.5 KB)

    init_kernel<<<512, 256>>>(N);
    gemm_hist_kernel<<<G + HB, 256, smem>>>(feat, W, bg, row_idx, N, F, E, G);
    scan_kernel<<<nscan, SCAN_BLK>>>(N, E);
    scatter_kernel<<<eb4, 256>>>(row_idx, col_idx, vv, E);
    agg_sdst_kernel<<<wb, 256>>>(wm, N);
    mz_kernel<<<wb, 256>>>(N);
    final_kernel<<<eb4, 256>>>(row_idx, col_idx, vv, out, E);
}